// round 12
// baseline (speedup 1.0000x reference)
#include <cuda_runtime.h>
#include <math.h>

// ---------------------------------------------------------------------------
// Problem constants
// ---------------------------------------------------------------------------
#define Bc   4
#define Lc   2048
#define DINc 80
#define Dc   128
#define Hc   16
#define DHc  8
#define DFFc 128
#define WINc 64
#define Mrows (Bc * Lc)        // 8192

// ---------------------------------------------------------------------------
// Scratch (device globals: allocation-free)
// ---------------------------------------------------------------------------
__device__ float g_h  [Mrows * Dc];        // post conv+bn+pe
__device__ float g_q  [Bc * Hc * Lc * DHc];
__device__ float g_kb [Bc * Hc * Lc * DHc];
__device__ float g_vb [Bc * Hc * Lc * DHc];
__device__ float g_ctx[Mrows * Dc];
__device__ float g_ao [Mrows * Dc];
__device__ float g_f  [Mrows * DFFc];
__device__ float g_g2 [Mrows * Dc];
__device__ float g_pe [Lc * Dc];

// ---------------------------------------------------------------------------
// Positional encoding table: pe[l][d], d pair j=d>>1, even->sin, odd->cos,
// divisor 10000^(j/128)  (faithful to the reference's exponent j/d)
// ---------------------------------------------------------------------------
__global__ void pe_kernel(float* __restrict__ pe) {
    int l = blockIdx.x;
    int d = threadIdx.x;
    int j = d >> 1;
    float pj  = powf(10000.0f, (float)j / 128.0f);
    float ang = (float)l / pj;
    pe[l * Dc + d] = (d & 1) ? cosf(ang) : sinf(ang);
}

// ---------------------------------------------------------------------------
// Tiled SGEMM: C[M,N] = A[M,K] @ W[N,K]^T (+ bias, + mode-specific epilogue)
// BM=BN=64, BK=64 chunked, 256 threads, 4x4 micro-tile per thread.
// Smem tiles stored K-major-transposed so inner loop is float4 LDS.
// MODE: 0 = bias        1 = bias+relu
//       2 = relu -> batchnorm -> +pe   (e0=g, e1=b, e2=rm, e3=rv, e4=pe)
//       3 = qkv scatter to [B,H,L,DH]  (C=q, o1=k, o2=v)
// ---------------------------------------------------------------------------
template <int MODE>
__global__ void __launch_bounds__(256)
gemm_k(const float* __restrict__ A, const float* __restrict__ W,
       const float* __restrict__ bias, float* __restrict__ C,
       int M, int N, int K,
       const float* __restrict__ e0, const float* __restrict__ e1,
       const float* __restrict__ e2, const float* __restrict__ e3,
       const float* __restrict__ e4,
       float* __restrict__ o1, float* __restrict__ o2)
{
    __shared__ float As[64][64];   // As[k][m]
    __shared__ float Ws[64][64];   // Ws[k][n]

    const int tid  = threadIdx.x;
    const int tx   = tid & 15;     // col group
    const int ty   = tid >> 4;     // row group
    const int row0 = blockIdx.y * 64;
    const int col0 = blockIdx.x * 64;

    float acc[4][4] = {};

    for (int k0 = 0; k0 < K; k0 += 64) {
        const int kc = min(64, K - k0);

        for (int idx = tid; idx < 64 * kc; idx += 256) {
            int m  = idx / kc;
            int kk = idx - m * kc;
            As[kk][m] = A[(size_t)(row0 + m) * K + k0 + kk];
        }
        for (int idx = tid; idx < 64 * kc; idx += 256) {
            int n  = idx / kc;
            int kk = idx - n * kc;
            Ws[kk][n] = (col0 + n < N) ? W[(size_t)(col0 + n) * K + k0 + kk] : 0.0f;
        }
        __syncthreads();

        #pragma unroll 8
        for (int kk = 0; kk < kc; kk++) {
            float4 a4 = *(const float4*)&As[kk][ty * 4];
            float4 w4 = *(const float4*)&Ws[kk][tx * 4];
            float av[4] = {a4.x, a4.y, a4.z, a4.w};
            float wv[4] = {w4.x, w4.y, w4.z, w4.w};
            #pragma unroll
            for (int i = 0; i < 4; i++)
                #pragma unroll
                for (int j = 0; j < 4; j++)
                    acc[i][j] += av[i] * wv[j];
        }
        __syncthreads();
    }

    #pragma unroll
    for (int i = 0; i < 4; i++) {
        const int m = row0 + ty * 4 + i;
        #pragma unroll
        for (int j = 0; j < 4; j++) {
            const int col = col0 + tx * 4 + j;
            if (col >= N) continue;
            float v = acc[i][j] + bias[col];
            if (MODE == 0) {
                C[(size_t)m * N + col] = v;
            } else if (MODE == 1) {
                C[(size_t)m * N + col] = fmaxf(v, 0.0f);
            } else if (MODE == 2) {
                v = fmaxf(v, 0.0f);
                v = (v - e2[col]) * (e0[col] * rsqrtf(e3[col] + 1e-5f)) + e1[col];
                int l = m & (Lc - 1);
                v += e4[l * Dc + col];
                C[(size_t)m * Dc + col] = v;
            } else {  // MODE 3: qkv scatter
                int b     = m >> 11;          // m / L
                int l     = m & (Lc - 1);
                int which = col >> 7;         // 0:q 1:k 2:v
                int d     = col & 127;
                int hh    = d >> 3;
                int dh    = d & 7;
                float* dst = (which == 0) ? C : ((which == 1) ? o1 : o2);
                dst[(((size_t)(b * Hc + hh)) * Lc + l) * DHc + dh] = v;
            }
        }
    }
}

// ---------------------------------------------------------------------------
// Local-window attention: one warp per (b,h,q).
// Window: keys j with 1 <= |j-q| <= 64 (diagonal EXCLUDED), clipped to [0,L).
// q/k/v layout: [B,H,L,8] contiguous. ctx written as [B,L,H*8] = [B,L,128].
// ---------------------------------------------------------------------------
__global__ void __launch_bounds__(256)
attn_kernel(const float* __restrict__ Q, const float* __restrict__ Kb,
            const float* __restrict__ Vb, float* __restrict__ ctx)
{
    const int warp = blockIdx.x * (blockDim.x >> 5) + (threadIdx.x >> 5);
    const int lane = threadIdx.x & 31;
    const int qpos = warp & (Lc - 1);
    const int bh   = warp >> 11;                 // b*H + h, 0..63

    const float* qp = Q  + ((size_t)bh * Lc + qpos) * DHc;
    const float* kp = Kb + (size_t)bh * Lc * DHc;
    const float* vp = Vb + (size_t)bh * Lc * DHc;

    const float4 q0 = *(const float4*)qp;
    const float4 q1 = *(const float4*)(qp + 4);

    int lo = qpos - WINc; if (lo < 0) lo = 0;
    int hi = qpos + WINc; if (hi > Lc - 1) hi = Lc - 1;

    const float scale = 0.35355339059327373f;    // 1/sqrt(8)

    float sc[5];
    float mx = -INFINITY;
    #pragma unroll
    for (int i = 0; i < 5; i++) {
        const int j = lo + lane + 32 * i;
        float s = -INFINITY;
        if (j <= hi && j != qpos) {
            const float4* kr = (const float4*)(kp + (size_t)j * DHc);
            float4 k0 = kr[0], k1 = kr[1];
            s = q0.x * k0.x + q0.y * k0.y + q0.z * k0.z + q0.w * k0.w
              + q1.x * k1.x + q1.y * k1.y + q1.z * k1.z + q1.w * k1.w;
            s *= scale;
            mx = fmaxf(mx, s);
        }
        sc[i] = s;
    }
    #pragma unroll
    for (int o = 16; o; o >>= 1)
        mx = fmaxf(mx, __shfl_xor_sync(0xffffffffu, mx, o));

    float sum = 0.0f;
    float c[8] = {0, 0, 0, 0, 0, 0, 0, 0};
    #pragma unroll
    for (int i = 0; i < 5; i++) {
        const int j = lo + lane + 32 * i;
        if (sc[i] != -INFINITY) {
            const float p = __expf(sc[i] - mx);
            sum += p;
            const float4* vr = (const float4*)(vp + (size_t)j * DHc);
            float4 v0 = vr[0], v1 = vr[1];
            c[0] += p * v0.x; c[1] += p * v0.y; c[2] += p * v0.z; c[3] += p * v0.w;
            c[4] += p * v1.x; c[5] += p * v1.y; c[6] += p * v1.z; c[7] += p * v1.w;
        }
    }
    #pragma unroll
    for (int o = 16; o; o >>= 1) {
        sum += __shfl_xor_sync(0xffffffffu, sum, o);
        #pragma unroll
        for (int d = 0; d < 8; d++)
            c[d] += __shfl_xor_sync(0xffffffffu, c[d], o);
    }

    if (lane < 8) {
        const float inv = 1.0f / sum;
        float val = 0.0f;
        #pragma unroll
        for (int d = 0; d < 8; d++)
            if (lane == d) val = c[d];
        const int hh = bh & (Hc - 1);
        const int b  = bh >> 4;
        ctx[((size_t)(b * Lc + qpos)) * Dc + hh * DHc + lane] = val * inv;
    }
}

// ---------------------------------------------------------------------------
// Launch
// ---------------------------------------------------------------------------
extern "C" void kernel_launch(void* const* d_in, const int* in_sizes, int n_in,
                              void* d_out, int out_size)
{
    const float* x         = (const float*)d_in[0];
    const float* conv_w    = (const float*)d_in[1];
    const float* conv_b    = (const float*)d_in[2];
    const float* bn_g      = (const float*)d_in[3];
    const float* bn_b      = (const float*)d_in[4];
    const float* bn_rm     = (const float*)d_in[5];
    const float* bn_rv     = (const float*)d_in[6];
    const float* in_proj_w = (const float*)d_in[7];
    const float* in_proj_b = (const float*)d_in[8];
    const float* out_w     = (const float*)d_in[9];
    const float* out_b     = (const float*)d_in[10];
    const float* ff_w1     = (const float*)d_in[11];
    const float* ff_b1     = (const float*)d_in[12];
    const float* ff_w2     = (const float*)d_in[13];
    const float* ff_b2     = (const float*)d_in[14];
    const float* fc_w      = (const float*)d_in[15];
    const float* fc_b      = (const float*)d_in[16];
    float* out = (float*)d_out;

    float *h, *q, *kb, *vb, *ctx, *ao, *f, *g2, *pe;
    cudaGetSymbolAddress((void**)&h,   g_h);
    cudaGetSymbolAddress((void**)&q,   g_q);
    cudaGetSymbolAddress((void**)&kb,  g_kb);
    cudaGetSymbolAddress((void**)&vb,  g_vb);
    cudaGetSymbolAddress((void**)&ctx, g_ctx);
    cudaGetSymbolAddress((void**)&ao,  g_ao);
    cudaGetSymbolAddress((void**)&f,   g_f);
    cudaGetSymbolAddress((void**)&g2,  g_g2);
    cudaGetSymbolAddress((void**)&pe,  g_pe);

    // 0) positional encoding table
    pe_kernel<<<Lc, Dc>>>(pe);

    // 1) conv(k=1) + relu + batchnorm + pe : [8192,80]x[128,80]^T -> h
    gemm_k<2><<<dim3(2, Mrows / 64), 256>>>(x, conv_w, conv_b, h,
        Mrows, Dc, DINc, bn_g, bn_b, bn_rm, bn_rv, pe, nullptr, nullptr);

    // 2) qkv projection with scatter to [B,H,L,8]
    gemm_k<3><<<dim3(6, Mrows / 64), 256>>>(h, in_proj_w, in_proj_b, q,
        Mrows, 3 * Dc, Dc, nullptr, nullptr, nullptr, nullptr, nullptr, kb, vb);

    // 3) local-window attention -> ctx [B,L,128]
    attn_kernel<<<(Bc * Hc * Lc) / 8, 256>>>(q, kb, vb, ctx);

    // 4) out projection
    gemm_k<0><<<dim3(2, Mrows / 64), 256>>>(ctx, out_w, out_b, ao,
        Mrows, Dc, Dc, nullptr, nullptr, nullptr, nullptr, nullptr, nullptr, nullptr);

    // 5) ffn layer 1 (relu)
    gemm_k<1><<<dim3(2, Mrows / 64), 256>>>(ao, ff_w1, ff_b1, f,
        Mrows, DFFc, Dc, nullptr, nullptr, nullptr, nullptr, nullptr, nullptr, nullptr);

    // 6) ffn layer 2
    gemm_k<0><<<dim3(2, Mrows / 64), 256>>>(f, ff_w2, ff_b2, g2,
        Mrows, Dc, DFFc, nullptr, nullptr, nullptr, nullptr, nullptr, nullptr, nullptr);

    // 7) final head -> d_out [8192,80]
    gemm_k<0><<<dim3(2, Mrows / 64), 256>>>(g2, fc_w, fc_b, out,
        Mrows, DINc, Dc, nullptr, nullptr, nullptr, nullptr, nullptr, nullptr, nullptr);
}

// round 13
// speedup vs baseline: 1.9239x; 1.9239x over previous
#include <cuda_runtime.h>
#include <math.h>

// ---------------------------------------------------------------------------
// Problem constants
// ---------------------------------------------------------------------------
#define Bc   4
#define Lc   2048
#define DINc 80
#define Dc   128
#define Hc   16
#define DHc  8
#define DFFc 128
#define WINc 64
#define Mrows (Bc * Lc)        // 8192

typedef unsigned long long ull;

// ---------------------------------------------------------------------------
// Scratch (device globals: allocation-free)
// ---------------------------------------------------------------------------
__device__ float g_h  [Mrows * Dc];
__device__ float g_q  [Bc * Hc * Lc * DHc];   // [B,H,L,8]
__device__ float g_kb [Bc * Hc * Lc * DHc];
__device__ float g_vb [Bc * Hc * Lc * DHc];
__device__ float g_ctx[Mrows * Dc];
__device__ float g_ao [Mrows * Dc];
__device__ float g_f  [Mrows * DFFc];
__device__ float g_g2 [Mrows * Dc];
__device__ float g_pe [Lc * Dc];

// ---------------------------------------------------------------------------
// f32x2 packed-FMA helpers (PTX-only on sm_103a; doubles fp32 FMA throughput)
// ---------------------------------------------------------------------------
__device__ __forceinline__ ull pack2(float x, float y) {
    ull r; asm("mov.b64 %0, {%1, %2};" : "=l"(r) : "f"(x), "f"(y)); return r;
}
__device__ __forceinline__ void unpack2(ull v, float& x, float& y) {
    asm("mov.b64 {%0, %1}, %2;" : "=f"(x), "=f"(y) : "l"(v));
}
__device__ __forceinline__ void fma2(ull& d, ull a, ull b) {
    asm("fma.rn.f32x2 %0, %1, %2, %0;" : "+l"(d) : "l"(a), "l"(b));
}

// ---------------------------------------------------------------------------
// Positional encoding: pair j=d>>1, even->sin, odd->cos, 10000^(j/128)
// ---------------------------------------------------------------------------
__global__ void pe_kernel(float* __restrict__ pe) {
    int l = blockIdx.x;
    int d = threadIdx.x;
    int j = d >> 1;
    float pj  = powf(10000.0f, (float)j / 128.0f);
    float ang = (float)l / pj;
    pe[l * Dc + d] = (d & 1) ? cosf(ang) : sinf(ang);
}

// ---------------------------------------------------------------------------
// Tiled SGEMM: C[M,N] = A[M,K] @ W[N,K]^T (+bias, +epilogue)
// BM=BN=64, BK=64, 256 threads, 4x4 micro-tile, f32x2 inner loop.
// Smem transposed tiles (As[k][m], Ws[k][n]); fill is conflict-free:
// each thread loads one A/W row's float4s and scatters scalars with m/n
// varying across lanes (consecutive banks).
// MODE: 0 bias | 1 bias+relu | 2 relu->BN->+pe | 3 qkv scatter [B,H,L,8]
// ---------------------------------------------------------------------------
template <int MODE>
__global__ void __launch_bounds__(256)
gemm_k(const float* __restrict__ A, const float* __restrict__ W,
       const float* __restrict__ bias, float* __restrict__ C,
       int M, int N, int K,
       const float* __restrict__ e0, const float* __restrict__ e1,
       const float* __restrict__ e2, const float* __restrict__ e3,
       const float* __restrict__ e4,
       float* __restrict__ o1, float* __restrict__ o2)
{
    __shared__ float As[64][64];   // As[k][m]
    __shared__ float Ws[64][64];   // Ws[k][n]

    const int tid  = threadIdx.x;
    const int tx   = tid & 15;
    const int ty   = tid >> 4;
    const int row0 = blockIdx.y * 64;
    const int col0 = blockIdx.x * 64;

    // fill assignment: one (row, 16-wide k-chunk) per thread
    const int mf = tid & 63;       // row/col within tile
    const int kq = tid >> 6;       // 0..3 -> k range [kq*16, kq*16+16)

    ull acc[4][2];
    #pragma unroll
    for (int i = 0; i < 4; i++) { acc[i][0] = 0ull; acc[i][1] = 0ull; }

    const bool wvalid = (col0 + mf) < N;

    for (int k0 = 0; k0 < K; k0 += 64) {
        const int kc = min(64, K - k0);   // 64 or 16 here (K in {80,128})

        const float* Ap = A + (size_t)(row0 + mf) * K + k0 + kq * 16;
        const float* Wp = W + (size_t)(col0 + mf) * K + k0 + kq * 16;
        #pragma unroll
        for (int u = 0; u < 4; u++) {
            const int kk = kq * 16 + u * 4;
            if (kk < kc) {
                float4 a4 = *(const float4*)(Ap + u * 4);
                As[kk + 0][mf] = a4.x; As[kk + 1][mf] = a4.y;
                As[kk + 2][mf] = a4.z; As[kk + 3][mf] = a4.w;
                float4 w4 = wvalid ? *(const float4*)(Wp + u * 4)
                                   : make_float4(0.f, 0.f, 0.f, 0.f);
                Ws[kk + 0][mf] = w4.x; Ws[kk + 1][mf] = w4.y;
                Ws[kk + 2][mf] = w4.z; Ws[kk + 3][mf] = w4.w;
            }
        }
        __syncthreads();

        #pragma unroll 8
        for (int kk = 0; kk < kc; kk++) {
            float4 a4 = *(const float4*)&As[kk][ty * 4];
            float4 w4 = *(const float4*)&Ws[kk][tx * 4];
            ull w01 = pack2(w4.x, w4.y);
            ull w23 = pack2(w4.z, w4.w);
            ull a0 = pack2(a4.x, a4.x);
            ull a1 = pack2(a4.y, a4.y);
            ull a2 = pack2(a4.z, a4.z);
            ull a3 = pack2(a4.w, a4.w);
            fma2(acc[0][0], a0, w01); fma2(acc[0][1], a0, w23);
            fma2(acc[1][0], a1, w01); fma2(acc[1][1], a1, w23);
            fma2(acc[2][0], a2, w01); fma2(acc[2][1], a2, w23);
            fma2(acc[3][0], a3, w01); fma2(acc[3][1], a3, w23);
        }
        __syncthreads();
    }

    #pragma unroll
    for (int i = 0; i < 4; i++) {
        const int m = row0 + ty * 4 + i;
        float av[4];
        unpack2(acc[i][0], av[0], av[1]);
        unpack2(acc[i][1], av[2], av[3]);
        #pragma unroll
        for (int j = 0; j < 4; j++) {
            const int col = col0 + tx * 4 + j;
            if (col >= N) continue;
            float v = av[j] + bias[col];
            if (MODE == 0) {
                C[(size_t)m * N + col] = v;
            } else if (MODE == 1) {
                C[(size_t)m * N + col] = fmaxf(v, 0.0f);
            } else if (MODE == 2) {
                v = fmaxf(v, 0.0f);
                v = (v - e2[col]) * (e0[col] * rsqrtf(e3[col] + 1e-5f)) + e1[col];
                int l = m & (Lc - 1);
                v += e4[l * Dc + col];
                C[(size_t)m * Dc + col] = v;
            } else {  // MODE 3: qkv scatter -> [B,H,L,8]
                int b     = m >> 11;
                int l     = m & (Lc - 1);
                int which = col >> 7;
                int d     = col & 127;
                int hh    = d >> 3;
                int dh    = d & 7;
                float* dst = (which == 0) ? C : ((which == 1) ? o1 : o2);
                dst[(((size_t)(b * Hc + hh)) * Lc + l) * DHc + dh] = v;
            }
        }
    }
}

// ---------------------------------------------------------------------------
// Local-window attention, thread-per-query with smem-staged d-major K/V.
// Block: 256 threads = 256 consecutive queries of one (b,h).
// Stages K/V rows [q0-64, q0+319] (384 rows) transposed to Kt[8][STR] so each
// key-dim load across the warp hits consecutive banks (1 wavefront / LDS).
// Window: 1 <= |j-q| <= 64 (diagonal excluded). Softmax w/o max-subtraction
// (|score| small; ratio exact in fp32).
// ---------------------------------------------------------------------------
#define ASTR 392   // padded 384 (stride%32==8 -> at most 2-way on stage stores)

__global__ void __launch_bounds__(256)
attn_kernel(const float* __restrict__ Q, const float* __restrict__ Kb,
            const float* __restrict__ Vb, float* __restrict__ ctx)
{
    __shared__ float Kt[DHc][ASTR];
    __shared__ float Vt[DHc][ASTR];

    const int tid = threadIdx.x;
    const int q0  = blockIdx.x * 256;
    const int bh  = blockIdx.y;               // b*H + h

    const float* kp = Kb + (size_t)bh * Lc * DHc;
    const float* vp = Vb + (size_t)bh * Lc * DHc;

    // stage 384 rows (clipped) transposed
    for (int idx = tid; idx < 384 * DHc; idx += 256) {
        const int r = idx >> 3;
        const int d = idx & 7;
        const int g = q0 - WINc + r;
        if (g >= 0 && g < Lc) {
            Kt[d][r] = kp[(size_t)g * DHc + d];
            Vt[d][r] = vp[(size_t)g * DHc + d];
        }
    }
    __syncthreads();

    const int q = q0 + tid;
    const float* qp = Q + ((size_t)bh * Lc + q) * DHc;
    float qr[DHc];
    {
        float4 q0v = *(const float4*)qp;
        float4 q1v = *(const float4*)(qp + 4);
        qr[0] = q0v.x; qr[1] = q0v.y; qr[2] = q0v.z; qr[3] = q0v.w;
        qr[4] = q1v.x; qr[5] = q1v.y; qr[6] = q1v.z; qr[7] = q1v.w;
    }

    const float scale = 0.35355339059327373f;  // 1/sqrt(8)
    float sum = 0.0f;
    float c[DHc] = {0, 0, 0, 0, 0, 0, 0, 0};

    #pragma unroll 4
    for (int off = -WINc; off <= WINc; off++) {
        const int j = q + off;
        if (off != 0 && j >= 0 && j < Lc) {
            const int rl = tid + off + WINc;     // local row, in [0,384)
            float s = 0.0f;
            #pragma unroll
            for (int d = 0; d < DHc; d++) s += qr[d] * Kt[d][rl];
            const float p = __expf(s * scale);
            sum += p;
            #pragma unroll
            for (int d = 0; d < DHc; d++) c[d] += p * Vt[d][rl];
        }
    }

    const float inv = 1.0f / sum;
    const int hh = bh & (Hc - 1);
    const int b  = bh >> 4;
    float* op = ctx + ((size_t)(b * Lc + q)) * Dc + hh * DHc;
    #pragma unroll
    for (int d = 0; d < DHc; d++) op[d] = c[d] * inv;
}

// ---------------------------------------------------------------------------
// Launch
// ---------------------------------------------------------------------------
extern "C" void kernel_launch(void* const* d_in, const int* in_sizes, int n_in,
                              void* d_out, int out_size)
{
    const float* x         = (const float*)d_in[0];
    const float* conv_w    = (const float*)d_in[1];
    const float* conv_b    = (const float*)d_in[2];
    const float* bn_g      = (const float*)d_in[3];
    const float* bn_b      = (const float*)d_in[4];
    const float* bn_rm     = (const float*)d_in[5];
    const float* bn_rv     = (const float*)d_in[6];
    const float* in_proj_w = (const float*)d_in[7];
    const float* in_proj_b = (const float*)d_in[8];
    const float* out_w     = (const float*)d_in[9];
    const float* out_b     = (const float*)d_in[10];
    const float* ff_w1     = (const float*)d_in[11];
    const float* ff_b1     = (const float*)d_in[12];
    const float* ff_w2     = (const float*)d_in[13];
    const float* ff_b2     = (const float*)d_in[14];
    const float* fc_w      = (const float*)d_in[15];
    const float* fc_b      = (const float*)d_in[16];
    float* out = (float*)d_out;

    float *h, *q, *kb, *vb, *ctx, *ao, *f, *g2, *pe;
    cudaGetSymbolAddress((void**)&h,   g_h);
    cudaGetSymbolAddress((void**)&q,   g_q);
    cudaGetSymbolAddress((void**)&kb,  g_kb);
    cudaGetSymbolAddress((void**)&vb,  g_vb);
    cudaGetSymbolAddress((void**)&ctx, g_ctx);
    cudaGetSymbolAddress((void**)&ao,  g_ao);
    cudaGetSymbolAddress((void**)&f,   g_f);
    cudaGetSymbolAddress((void**)&g2,  g_g2);
    cudaGetSymbolAddress((void**)&pe,  g_pe);

    // 0) positional encoding
    pe_kernel<<<Lc, Dc>>>(pe);

    // 1) conv(k=1)+relu+BN+pe
    gemm_k<2><<<dim3(2, Mrows / 64), 256>>>(x, conv_w, conv_b, h,
        Mrows, Dc, DINc, bn_g, bn_b, bn_rm, bn_rv, pe, nullptr, nullptr);

    // 2) qkv projection, scatter to [B,H,L,8]
    gemm_k<3><<<dim3(6, Mrows / 64), 256>>>(h, in_proj_w, in_proj_b, q,
        Mrows, 3 * Dc, Dc, nullptr, nullptr, nullptr, nullptr, nullptr, kb, vb);

    // 3) local-window attention -> ctx [B,L,128]
    attn_kernel<<<dim3(Lc / 256, Bc * Hc), 256>>>(q, kb, vb, ctx);

    // 4) out projection
    gemm_k<0><<<dim3(2, Mrows / 64), 256>>>(ctx, out_w, out_b, ao,
        Mrows, Dc, Dc, nullptr, nullptr, nullptr, nullptr, nullptr, nullptr, nullptr);

    // 5) ffn layer 1 (relu)
    gemm_k<1><<<dim3(2, Mrows / 64), 256>>>(ao, ff_w1, ff_b1, f,
        Mrows, DFFc, Dc, nullptr, nullptr, nullptr, nullptr, nullptr, nullptr, nullptr);

    // 6) ffn layer 2
    gemm_k<0><<<dim3(2, Mrows / 64), 256>>>(f, ff_w2, ff_b2, g2,
        Mrows, Dc, DFFc, nullptr, nullptr, nullptr, nullptr, nullptr, nullptr, nullptr);

    // 7) final head -> [8192,80]
    gemm_k<0><<<dim3(2, Mrows / 64), 256>>>(g2, fc_w, fc_b, out,
        Mrows, DINc, Dc, nullptr, nullptr, nullptr, nullptr, nullptr, nullptr, nullptr);
}

// round 14
// speedup vs baseline: 1.9250x; 1.0006x over previous
#include <cuda_runtime.h>
#include <math.h>

// ---------------------------------------------------------------------------
// Problem constants
// ---------------------------------------------------------------------------
#define Bc   4
#define Lc   2048
#define DINc 80
#define Dc   128
#define Hc   16
#define DHc  8
#define DFFc 128
#define WINc 64
#define Mrows (Bc * Lc)        // 8192

typedef unsigned long long ull;

// ---------------------------------------------------------------------------
// Scratch (device globals: allocation-free)
// ---------------------------------------------------------------------------
__device__ float g_h  [Mrows * Dc];
__device__ float g_q  [Bc * Hc * Lc * DHc];   // [B,H,L,8]
__device__ float g_kb [Bc * Hc * Lc * DHc];
__device__ float g_vb [Bc * Hc * Lc * DHc];
__device__ float g_ctx[Mrows * Dc];
__device__ float g_ao [Mrows * Dc];
__device__ float g_f  [Mrows * DFFc];
__device__ float g_g2 [Mrows * Dc];
__device__ float g_pe [Lc * Dc];

// ---------------------------------------------------------------------------
// f32x2 packed-FMA helpers (PTX-only on sm_103a; doubles fp32 FMA throughput)
// ---------------------------------------------------------------------------
__device__ __forceinline__ ull pack2(float x, float y) {
    ull r; asm("mov.b64 %0, {%1, %2};" : "=l"(r) : "f"(x), "f"(y)); return r;
}
__device__ __forceinline__ void unpack2(ull v, float& x, float& y) {
    asm("mov.b64 {%0, %1}, %2;" : "=f"(x), "=f"(y) : "l"(v));
}
__device__ __forceinline__ void fma2(ull& d, ull a, ull b) {
    asm("fma.rn.f32x2 %0, %1, %2, %0;" : "+l"(d) : "l"(a), "l"(b));
}

// ---------------------------------------------------------------------------
// Positional encoding: pair j=d>>1, even->sin, odd->cos, 10000^(j/128)
// ---------------------------------------------------------------------------
__global__ void pe_kernel(float* __restrict__ pe) {
    int l = blockIdx.x;
    int d = threadIdx.x;
    int j = d >> 1;
    float pj  = powf(10000.0f, (float)j / 128.0f);
    float ang = (float)l / pj;
    pe[l * Dc + d] = (d & 1) ? cosf(ang) : sinf(ang);
}

// ---------------------------------------------------------------------------
// Tiled SGEMM: C[M,N] = A[M,K] @ W[N,K]^T (+bias, +epilogue)
// BM=BN=64, BK=64, 256 threads, 4x4 micro-tile, f32x2 inner loop.
// Smem transposed tiles (As[k][m], Ws[k][n]); fill is conflict-free:
// each thread loads one A/W row's float4s and scatters scalars with m/n
// varying across lanes (consecutive banks).
// MODE: 0 bias | 1 bias+relu | 2 relu->BN->+pe | 3 qkv scatter [B,H,L,8]
// ---------------------------------------------------------------------------
template <int MODE>
__global__ void __launch_bounds__(256)
gemm_k(const float* __restrict__ A, const float* __restrict__ W,
       const float* __restrict__ bias, float* __restrict__ C,
       int M, int N, int K,
       const float* __restrict__ e0, const float* __restrict__ e1,
       const float* __restrict__ e2, const float* __restrict__ e3,
       const float* __restrict__ e4,
       float* __restrict__ o1, float* __restrict__ o2)
{
    __shared__ float As[64][64];   // As[k][m]
    __shared__ float Ws[64][64];   // Ws[k][n]

    const int tid  = threadIdx.x;
    const int tx   = tid & 15;
    const int ty   = tid >> 4;
    const int row0 = blockIdx.y * 64;
    const int col0 = blockIdx.x * 64;

    // fill assignment: one (row, 16-wide k-chunk) per thread
    const int mf = tid & 63;       // row/col within tile
    const int kq = tid >> 6;       // 0..3 -> k range [kq*16, kq*16+16)

    ull acc[4][2];
    #pragma unroll
    for (int i = 0; i < 4; i++) { acc[i][0] = 0ull; acc[i][1] = 0ull; }

    const bool wvalid = (col0 + mf) < N;

    for (int k0 = 0; k0 < K; k0 += 64) {
        const int kc = min(64, K - k0);   // 64 or 16 here (K in {80,128})

        const float* Ap = A + (size_t)(row0 + mf) * K + k0 + kq * 16;
        const float* Wp = W + (size_t)(col0 + mf) * K + k0 + kq * 16;
        #pragma unroll
        for (int u = 0; u < 4; u++) {
            const int kk = kq * 16 + u * 4;
            if (kk < kc) {
                float4 a4 = *(const float4*)(Ap + u * 4);
                As[kk + 0][mf] = a4.x; As[kk + 1][mf] = a4.y;
                As[kk + 2][mf] = a4.z; As[kk + 3][mf] = a4.w;
                float4 w4 = wvalid ? *(const float4*)(Wp + u * 4)
                                   : make_float4(0.f, 0.f, 0.f, 0.f);
                Ws[kk + 0][mf] = w4.x; Ws[kk + 1][mf] = w4.y;
                Ws[kk + 2][mf] = w4.z; Ws[kk + 3][mf] = w4.w;
            }
        }
        __syncthreads();

        #pragma unroll 8
        for (int kk = 0; kk < kc; kk++) {
            float4 a4 = *(const float4*)&As[kk][ty * 4];
            float4 w4 = *(const float4*)&Ws[kk][tx * 4];
            ull w01 = pack2(w4.x, w4.y);
            ull w23 = pack2(w4.z, w4.w);
            ull a0 = pack2(a4.x, a4.x);
            ull a1 = pack2(a4.y, a4.y);
            ull a2 = pack2(a4.z, a4.z);
            ull a3 = pack2(a4.w, a4.w);
            fma2(acc[0][0], a0, w01); fma2(acc[0][1], a0, w23);
            fma2(acc[1][0], a1, w01); fma2(acc[1][1], a1, w23);
            fma2(acc[2][0], a2, w01); fma2(acc[2][1], a2, w23);
            fma2(acc[3][0], a3, w01); fma2(acc[3][1], a3, w23);
        }
        __syncthreads();
    }

    #pragma unroll
    for (int i = 0; i < 4; i++) {
        const int m = row0 + ty * 4 + i;
        float av[4];
        unpack2(acc[i][0], av[0], av[1]);
        unpack2(acc[i][1], av[2], av[3]);
        #pragma unroll
        for (int j = 0; j < 4; j++) {
            const int col = col0 + tx * 4 + j;
            if (col >= N) continue;
            float v = av[j] + bias[col];
            if (MODE == 0) {
                C[(size_t)m * N + col] = v;
            } else if (MODE == 1) {
                C[(size_t)m * N + col] = fmaxf(v, 0.0f);
            } else if (MODE == 2) {
                v = fmaxf(v, 0.0f);
                v = (v - e2[col]) * (e0[col] * rsqrtf(e3[col] + 1e-5f)) + e1[col];
                int l = m & (Lc - 1);
                v += e4[l * Dc + col];
                C[(size_t)m * Dc + col] = v;
            } else {  // MODE 3: qkv scatter -> [B,H,L,8]
                int b     = m >> 11;
                int l     = m & (Lc - 1);
                int which = col >> 7;
                int d     = col & 127;
                int hh    = d >> 3;
                int dh    = d & 7;
                float* dst = (which == 0) ? C : ((which == 1) ? o1 : o2);
                dst[(((size_t)(b * Hc + hh)) * Lc + l) * DHc + dh] = v;
            }
        }
    }
}

// ---------------------------------------------------------------------------
// Local-window attention, thread-per-query with smem-staged d-major K/V.
// Block: 256 threads = 256 consecutive queries of one (b,h).
// Stages K/V rows [q0-64, q0+319] (384 rows) transposed to Kt[8][STR] so each
// key-dim load across the warp hits consecutive banks (1 wavefront / LDS).
// Window: 1 <= |j-q| <= 64 (diagonal excluded). Softmax w/o max-subtraction
// (|score| small; ratio exact in fp32).
// ---------------------------------------------------------------------------
#define ASTR 392   // padded 384 (stride%32==8 -> at most 2-way on stage stores)

__global__ void __launch_bounds__(256)
attn_kernel(const float* __restrict__ Q, const float* __restrict__ Kb,
            const float* __restrict__ Vb, float* __restrict__ ctx)
{
    __shared__ float Kt[DHc][ASTR];
    __shared__ float Vt[DHc][ASTR];

    const int tid = threadIdx.x;
    const int q0  = blockIdx.x * 256;
    const int bh  = blockIdx.y;               // b*H + h

    const float* kp = Kb + (size_t)bh * Lc * DHc;
    const float* vp = Vb + (size_t)bh * Lc * DHc;

    // stage 384 rows (clipped) transposed
    for (int idx = tid; idx < 384 * DHc; idx += 256) {
        const int r = idx >> 3;
        const int d = idx & 7;
        const int g = q0 - WINc + r;
        if (g >= 0 && g < Lc) {
            Kt[d][r] = kp[(size_t)g * DHc + d];
            Vt[d][r] = vp[(size_t)g * DHc + d];
        }
    }
    __syncthreads();

    const int q = q0 + tid;
    const float* qp = Q + ((size_t)bh * Lc + q) * DHc;
    float qr[DHc];
    {
        float4 q0v = *(const float4*)qp;
        float4 q1v = *(const float4*)(qp + 4);
        qr[0] = q0v.x; qr[1] = q0v.y; qr[2] = q0v.z; qr[3] = q0v.w;
        qr[4] = q1v.x; qr[5] = q1v.y; qr[6] = q1v.z; qr[7] = q1v.w;
    }

    const float scale = 0.35355339059327373f;  // 1/sqrt(8)
    float sum = 0.0f;
    float c[DHc] = {0, 0, 0, 0, 0, 0, 0, 0};

    #pragma unroll 4
    for (int off = -WINc; off <= WINc; off++) {
        const int j = q + off;
        if (off != 0 && j >= 0 && j < Lc) {
            const int rl = tid + off + WINc;     // local row, in [0,384)
            float s = 0.0f;
            #pragma unroll
            for (int d = 0; d < DHc; d++) s += qr[d] * Kt[d][rl];
            const float p = __expf(s * scale);
            sum += p;
            #pragma unroll
            for (int d = 0; d < DHc; d++) c[d] += p * Vt[d][rl];
        }
    }

    const float inv = 1.0f / sum;
    const int hh = bh & (Hc - 1);
    const int b  = bh >> 4;
    float* op = ctx + ((size_t)(b * Lc + q)) * Dc + hh * DHc;
    #pragma unroll
    for (int d = 0; d < DHc; d++) op[d] = c[d] * inv;
}

// ---------------------------------------------------------------------------
// Launch
// ---------------------------------------------------------------------------
extern "C" void kernel_launch(void* const* d_in, const int* in_sizes, int n_in,
                              void* d_out, int out_size)
{
    const float* x         = (const float*)d_in[0];
    const float* conv_w    = (const float*)d_in[1];
    const float* conv_b    = (const float*)d_in[2];
    const float* bn_g      = (const float*)d_in[3];
    const float* bn_b      = (const float*)d_in[4];
    const float* bn_rm     = (const float*)d_in[5];
    const float* bn_rv     = (const float*)d_in[6];
    const float* in_proj_w = (const float*)d_in[7];
    const float* in_proj_b = (const float*)d_in[8];
    const float* out_w     = (const float*)d_in[9];
    const float* out_b     = (const float*)d_in[10];
    const float* ff_w1     = (const float*)d_in[11];
    const float* ff_b1     = (const float*)d_in[12];
    const float* ff_w2     = (const float*)d_in[13];
    const float* ff_b2     = (const float*)d_in[14];
    const float* fc_w      = (const float*)d_in[15];
    const float* fc_b      = (const float*)d_in[16];
    float* out = (float*)d_out;

    float *h, *q, *kb, *vb, *ctx, *ao, *f, *g2, *pe;
    cudaGetSymbolAddress((void**)&h,   g_h);
    cudaGetSymbolAddress((void**)&q,   g_q);
    cudaGetSymbolAddress((void**)&kb,  g_kb);
    cudaGetSymbolAddress((void**)&vb,  g_vb);
    cudaGetSymbolAddress((void**)&ctx, g_ctx);
    cudaGetSymbolAddress((void**)&ao,  g_ao);
    cudaGetSymbolAddress((void**)&f,   g_f);
    cudaGetSymbolAddress((void**)&g2,  g_g2);
    cudaGetSymbolAddress((void**)&pe,  g_pe);

    // 0) positional encoding
    pe_kernel<<<Lc, Dc>>>(pe);

    // 1) conv(k=1)+relu+BN+pe
    gemm_k<2><<<dim3(2, Mrows / 64), 256>>>(x, conv_w, conv_b, h,
        Mrows, Dc, DINc, bn_g, bn_b, bn_rm, bn_rv, pe, nullptr, nullptr);

    // 2) qkv projection, scatter to [B,H,L,8]
    gemm_k<3><<<dim3(6, Mrows / 64), 256>>>(h, in_proj_w, in_proj_b, q,
        Mrows, 3 * Dc, Dc, nullptr, nullptr, nullptr, nullptr, nullptr, kb, vb);

    // 3) local-window attention -> ctx [B,L,128]
    attn_kernel<<<dim3(Lc / 256, Bc * Hc), 256>>>(q, kb, vb, ctx);

    // 4) out projection
    gemm_k<0><<<dim3(2, Mrows / 64), 256>>>(ctx, out_w, out_b, ao,
        Mrows, Dc, Dc, nullptr, nullptr, nullptr, nullptr, nullptr, nullptr, nullptr);

    // 5) ffn layer 1 (relu)
    gemm_k<1><<<dim3(2, Mrows / 64), 256>>>(ao, ff_w1, ff_b1, f,
        Mrows, DFFc, Dc, nullptr, nullptr, nullptr, nullptr, nullptr, nullptr, nullptr);

    // 6) ffn layer 2
    gemm_k<0><<<dim3(2, Mrows / 64), 256>>>(f, ff_w2, ff_b2, g2,
        Mrows, Dc, DFFc, nullptr, nullptr, nullptr, nullptr, nullptr, nullptr, nullptr);

    // 7) final head -> [8192,80]
    gemm_k<0><<<dim3(2, Mrows / 64), 256>>>(g2, fc_w, fc_b, out,
        Mrows, DINc, Dc, nullptr, nullptr, nullptr, nullptr, nullptr, nullptr, nullptr);
}

// round 15
// speedup vs baseline: 1.9486x; 1.0123x over previous
#include <cuda_runtime.h>
#include <math.h>

// ---------------------------------------------------------------------------
// Problem constants
// ---------------------------------------------------------------------------
#define Bc   4
#define Lc   2048
#define DINc 80
#define Dc   128
#define Hc   16
#define DHc  8
#define DFFc 128
#define WINc 64
#define Mrows (Bc * Lc)        // 8192

typedef unsigned long long ull;

// ---------------------------------------------------------------------------
// Scratch (device globals: allocation-free)
// ---------------------------------------------------------------------------
__device__ float g_h  [Mrows * Dc];
__device__ float g_q  [Bc * Hc * Lc * DHc];   // [B,H,L,8]
__device__ float g_kb [Bc * Hc * Lc * DHc];
__device__ float g_vb [Bc * Hc * Lc * DHc];
__device__ float g_ctx[Mrows * Dc];
__device__ float g_ao [Mrows * Dc];
__device__ float g_f  [Mrows * DFFc];
__device__ float g_g2 [Mrows * Dc];
__device__ float g_pe [Lc * Dc];

// ---------------------------------------------------------------------------
// f32x2 packed-FMA helpers (PTX-only; doubles fp32 FMA throughput on sm_103a)
// ---------------------------------------------------------------------------
__device__ __forceinline__ ull pack2(float x, float y) {
    ull r; asm("mov.b64 %0, {%1, %2};" : "=l"(r) : "f"(x), "f"(y)); return r;
}
__device__ __forceinline__ void unpack2(ull v, float& x, float& y) {
    asm("mov.b64 {%0, %1}, %2;" : "=f"(x), "=f"(y) : "l"(v));
}
__device__ __forceinline__ void fma2(ull& d, ull a, ull b) {
    asm("fma.rn.f32x2 %0, %1, %2, %0;" : "+l"(d) : "l"(a), "l"(b));
}

// ---------------------------------------------------------------------------
// Positional encoding: pair j=d>>1, even->sin, odd->cos, 10000^(j/128)
// ---------------------------------------------------------------------------
__global__ void pe_kernel(float* __restrict__ pe) {
    int l = blockIdx.x;
    int d = threadIdx.x;
    int j = d >> 1;
    float pj  = powf(10000.0f, (float)j / 128.0f);
    float ang = (float)l / pj;
    pe[l * Dc + d] = (d & 1) ? cosf(ang) : sinf(ang);
}

// ---------------------------------------------------------------------------
// Tiled SGEMM: C[M,N] = A[M,K] @ W[N,K]^T (+bias, +epilogue)
// BM=64, BN=128, BK=64, 256 threads, 4 rows x 8 cols per thread.
// W pairs come free from LDS (ulonglong2); only A is duplicated (4 packs/k).
// N in {80,128,384}: every 8-col thread group is fully in or fully out.
// MODE: 0 bias | 1 bias+relu | 2 relu->BN->+pe | 3 qkv scatter [B,H,L,8]
// ---------------------------------------------------------------------------
template <int MODE>
__global__ void __launch_bounds__(256)
gemm_k(const float* __restrict__ A, const float* __restrict__ W,
       const float* __restrict__ bias, float* __restrict__ C,
       int M, int N, int K,
       const float* __restrict__ e0, const float* __restrict__ e1,
       const float* __restrict__ e2, const float* __restrict__ e3,
       const float* __restrict__ e4,
       float* __restrict__ o1, float* __restrict__ o2)
{
    __shared__ float As[64][64];    // [k][m] 16 KB
    __shared__ float Ws[64][128];   // [k][n] 32 KB

    const int tid  = threadIdx.x;
    const int tx   = tid & 15;      // col group: 8 cols
    const int ty   = tid >> 4;      // row group: 4 rows
    const int row0 = blockIdx.y * 64;
    const int col0 = blockIdx.x * 128;

    // A-fill: row mf (0..63), k-chunk kq*16   (4 float4 per thread)
    const int mfA = tid & 63;
    const int kqA = tid >> 6;       // 0..3
    // W-fill: row nf (0..127), k-chunk kh*32  (8 float4 per thread)
    const int nfW = tid & 127;
    const int khW = tid >> 7;       // 0..1
    const bool wvalid = (col0 + nfW) < N;

    ull acc[4][4];
    #pragma unroll
    for (int i = 0; i < 4; i++)
        #pragma unroll
        for (int j = 0; j < 4; j++) acc[i][j] = 0ull;

    for (int k0 = 0; k0 < K; k0 += 64) {
        const int kc = min(64, K - k0);   // 64 or 16

        const float* Ap = A + (size_t)(row0 + mfA) * K + k0 + kqA * 16;
        #pragma unroll
        for (int u = 0; u < 4; u++) {
            const int kk = kqA * 16 + u * 4;
            if (kk < kc) {
                float4 a4 = *(const float4*)(Ap + u * 4);
                As[kk + 0][mfA] = a4.x; As[kk + 1][mfA] = a4.y;
                As[kk + 2][mfA] = a4.z; As[kk + 3][mfA] = a4.w;
            }
        }
        const float* Wp = W + (size_t)(col0 + nfW) * K + k0 + khW * 32;
        #pragma unroll
        for (int u = 0; u < 8; u++) {
            const int kk = khW * 32 + u * 4;
            if (kk < kc) {
                float4 w4 = wvalid ? *(const float4*)(Wp + u * 4)
                                   : make_float4(0.f, 0.f, 0.f, 0.f);
                Ws[kk + 0][nfW] = w4.x; Ws[kk + 1][nfW] = w4.y;
                Ws[kk + 2][nfW] = w4.z; Ws[kk + 3][nfW] = w4.w;
            }
        }
        __syncthreads();

        #pragma unroll 8
        for (int kk = 0; kk < kc; kk++) {
            float4 a4 = *(const float4*)&As[kk][ty * 4];
            ulonglong2 wA = *(const ulonglong2*)&Ws[kk][tx * 8];
            ulonglong2 wB = *(const ulonglong2*)&Ws[kk][tx * 8 + 4];
            ull d0 = pack2(a4.x, a4.x);
            ull d1 = pack2(a4.y, a4.y);
            ull d2 = pack2(a4.z, a4.z);
            ull d3 = pack2(a4.w, a4.w);
            fma2(acc[0][0], d0, wA.x); fma2(acc[0][1], d0, wA.y);
            fma2(acc[0][2], d0, wB.x); fma2(acc[0][3], d0, wB.y);
            fma2(acc[1][0], d1, wA.x); fma2(acc[1][1], d1, wA.y);
            fma2(acc[1][2], d1, wB.x); fma2(acc[1][3], d1, wB.y);
            fma2(acc[2][0], d2, wA.x); fma2(acc[2][1], d2, wA.y);
            fma2(acc[2][2], d2, wB.x); fma2(acc[2][3], d2, wB.y);
            fma2(acc[3][0], d3, wA.x); fma2(acc[3][1], d3, wA.y);
            fma2(acc[3][2], d3, wB.x); fma2(acc[3][3], d3, wB.y);
        }
        __syncthreads();
    }

    // ---- epilogue: this thread owns cols [colb, colb+8), fully in or out
    const int colb = col0 + tx * 8;
    if (colb + 7 >= N) return;

    float4 b0 = *(const float4*)(bias + colb);
    float4 b1 = *(const float4*)(bias + colb + 4);

    float4 g0, g1, be0, be1, rm0, rm1, rv0, rv1;   // MODE 2 params
    if (MODE == 2) {
        g0  = *(const float4*)(e0 + colb); g1  = *(const float4*)(e0 + colb + 4);
        be0 = *(const float4*)(e1 + colb); be1 = *(const float4*)(e1 + colb + 4);
        rm0 = *(const float4*)(e2 + colb); rm1 = *(const float4*)(e2 + colb + 4);
        rv0 = *(const float4*)(e3 + colb); rv1 = *(const float4*)(e3 + colb + 4);
        g0.x *= rsqrtf(rv0.x + 1e-5f); g0.y *= rsqrtf(rv0.y + 1e-5f);
        g0.z *= rsqrtf(rv0.z + 1e-5f); g0.w *= rsqrtf(rv0.w + 1e-5f);
        g1.x *= rsqrtf(rv1.x + 1e-5f); g1.y *= rsqrtf(rv1.y + 1e-5f);
        g1.z *= rsqrtf(rv1.z + 1e-5f); g1.w *= rsqrtf(rv1.w + 1e-5f);
    }

    #pragma unroll
    for (int i = 0; i < 4; i++) {
        const int m = row0 + ty * 4 + i;
        float v[8];
        unpack2(acc[i][0], v[0], v[1]);
        unpack2(acc[i][1], v[2], v[3]);
        unpack2(acc[i][2], v[4], v[5]);
        unpack2(acc[i][3], v[6], v[7]);
        v[0] += b0.x; v[1] += b0.y; v[2] += b0.z; v[3] += b0.w;
        v[4] += b1.x; v[5] += b1.y; v[6] += b1.z; v[7] += b1.w;

        if (MODE == 0 || MODE == 1) {
            if (MODE == 1)
                #pragma unroll
                for (int j = 0; j < 8; j++) v[j] = fmaxf(v[j], 0.0f);
            float* cp = C + (size_t)m * N + colb;
            *(float4*)cp       = make_float4(v[0], v[1], v[2], v[3]);
            *(float4*)(cp + 4) = make_float4(v[4], v[5], v[6], v[7]);
        } else if (MODE == 2) {
            const int l = m & (Lc - 1);
            float4 p0 = *(const float4*)(e4 + (size_t)l * Dc + colb);
            float4 p1 = *(const float4*)(e4 + (size_t)l * Dc + colb + 4);
            v[0] = fmaxf(v[0], 0.f); v[1] = fmaxf(v[1], 0.f);
            v[2] = fmaxf(v[2], 0.f); v[3] = fmaxf(v[3], 0.f);
            v[4] = fmaxf(v[4], 0.f); v[5] = fmaxf(v[5], 0.f);
            v[6] = fmaxf(v[6], 0.f); v[7] = fmaxf(v[7], 0.f);
            v[0] = (v[0] - rm0.x) * g0.x + be0.x + p0.x;
            v[1] = (v[1] - rm0.y) * g0.y + be0.y + p0.y;
            v[2] = (v[2] - rm0.z) * g0.z + be0.z + p0.z;
            v[3] = (v[3] - rm0.w) * g0.w + be0.w + p0.w;
            v[4] = (v[4] - rm1.x) * g1.x + be1.x + p1.x;
            v[5] = (v[5] - rm1.y) * g1.y + be1.y + p1.y;
            v[6] = (v[6] - rm1.z) * g1.z + be1.z + p1.z;
            v[7] = (v[7] - rm1.w) * g1.w + be1.w + p1.w;
            float* cp = C + (size_t)m * Dc + colb;
            *(float4*)cp       = make_float4(v[0], v[1], v[2], v[3]);
            *(float4*)(cp + 4) = make_float4(v[4], v[5], v[6], v[7]);
        } else {  // MODE 3: qkv scatter -> [B,H,L,8]; which/hh constant per thread
            const int which = col0 >> 7;          // 0:q 1:k 2:v (col0 in {0,128,256})
            const int hh = tx;                    // (colb & 127) >> 3
            const int b  = m >> 11;
            const int l  = m & (Lc - 1);
            float* dst = (which == 0) ? C : ((which == 1) ? o1 : o2);
            float* dp = dst + (((size_t)(b * Hc + hh)) * Lc + l) * DHc;
            *(float4*)dp       = make_float4(v[0], v[1], v[2], v[3]);
            *(float4*)(dp + 4) = make_float4(v[4], v[5], v[6], v[7]);
        }
    }
}

// ---------------------------------------------------------------------------
// Local-window attention, thread-per-query, d-pair float2 smem + f32x2 math.
// Block: 128 threads = 128 consecutive queries of one (b,h).
// Stages rows [q0-64, q0+191] (256 rows) as Kp[dp][r] = (K[r][2dp],K[r][2dp+1]).
// Window: 1 <= |j-q| <= 64 (diagonal excluded). Softmax w/o max-subtraction.
// ---------------------------------------------------------------------------
#define AQ    128
#define AROWS 256

__global__ void __launch_bounds__(AQ)
attn_kernel(const float* __restrict__ Q, const float* __restrict__ Kb,
            const float* __restrict__ Vb, float* __restrict__ ctx)
{
    __shared__ float2 Kp[4][AROWS];
    __shared__ float2 Vp[4][AROWS];

    const int tid = threadIdx.x;
    const int q0  = blockIdx.x * AQ;
    const int bh  = blockIdx.y;               // b*H + h

    const float* kp = Kb + (size_t)bh * Lc * DHc;
    const float* vp = Vb + (size_t)bh * Lc * DHc;

    #pragma unroll
    for (int rr = 0; rr < AROWS / AQ; rr++) {
        const int r = tid + rr * AQ;
        const int g = q0 - WINc + r;
        if (g >= 0 && g < Lc) {
            float4 k0 = *(const float4*)(kp + (size_t)g * DHc);
            float4 k1 = *(const float4*)(kp + (size_t)g * DHc + 4);
            Kp[0][r] = make_float2(k0.x, k0.y);
            Kp[1][r] = make_float2(k0.z, k0.w);
            Kp[2][r] = make_float2(k1.x, k1.y);
            Kp[3][r] = make_float2(k1.z, k1.w);
            float4 v0 = *(const float4*)(vp + (size_t)g * DHc);
            float4 v1 = *(const float4*)(vp + (size_t)g * DHc + 4);
            Vp[0][r] = make_float2(v0.x, v0.y);
            Vp[1][r] = make_float2(v0.z, v0.w);
            Vp[2][r] = make_float2(v1.x, v1.y);
            Vp[3][r] = make_float2(v1.z, v1.w);
        } else {
            Kp[0][r] = Kp[1][r] = Kp[2][r] = Kp[3][r] = make_float2(0.f, 0.f);
            Vp[0][r] = Vp[1][r] = Vp[2][r] = Vp[3][r] = make_float2(0.f, 0.f);
        }
    }
    __syncthreads();

    const int q = q0 + tid;
    const float* qp = Q + ((size_t)bh * Lc + q) * DHc;
    ull qd[4];
    {
        float4 qa = *(const float4*)qp;
        float4 qb = *(const float4*)(qp + 4);
        qd[0] = pack2(qa.x, qa.y); qd[1] = pack2(qa.z, qa.w);
        qd[2] = pack2(qb.x, qb.y); qd[3] = pack2(qb.z, qb.w);
    }

    const float scale = 0.35355339059327373f;  // 1/sqrt(8)
    float sum = 0.0f;
    ull c2[4] = {0ull, 0ull, 0ull, 0ull};

    #pragma unroll 4
    for (int off = -WINc; off < 0; off++) {
        if (q + off >= 0) {
            const int r = tid + off + WINc;
            ull s2 = 0ull;
            fma2(s2, qd[0], *(const ull*)&Kp[0][r]);
            fma2(s2, qd[1], *(const ull*)&Kp[1][r]);
            fma2(s2, qd[2], *(const ull*)&Kp[2][r]);
            fma2(s2, qd[3], *(const ull*)&Kp[3][r]);
            float slo, shi; unpack2(s2, slo, shi);
            const float p = __expf((slo + shi) * scale);
            sum += p;
            const ull p2 = pack2(p, p);
            fma2(c2[0], p2, *(const ull*)&Vp[0][r]);
            fma2(c2[1], p2, *(const ull*)&Vp[1][r]);
            fma2(c2[2], p2, *(const ull*)&Vp[2][r]);
            fma2(c2[3], p2, *(const ull*)&Vp[3][r]);
        }
    }
    #pragma unroll 4
    for (int off = 1; off <= WINc; off++) {
        if (q + off < Lc) {
            const int r = tid + off + WINc;
            ull s2 = 0ull;
            fma2(s2, qd[0], *(const ull*)&Kp[0][r]);
            fma2(s2, qd[1], *(const ull*)&Kp[1][r]);
            fma2(s2, qd[2], *(const ull*)&Kp[2][r]);
            fma2(s2, qd[3], *(const ull*)&Kp[3][r]);
            float slo, shi; unpack2(s2, slo, shi);
            const float p = __expf((slo + shi) * scale);
            sum += p;
            const ull p2 = pack2(p, p);
            fma2(c2[0], p2, *(const ull*)&Vp[0][r]);
            fma2(c2[1], p2, *(const ull*)&Vp[1][r]);
            fma2(c2[2], p2, *(const ull*)&Vp[2][r]);
            fma2(c2[3], p2, *(const ull*)&Vp[3][r]);
        }
    }

    const float inv = 1.0f / sum;
    float o[8];
    unpack2(c2[0], o[0], o[1]);
    unpack2(c2[1], o[2], o[3]);
    unpack2(c2[2], o[4], o[5]);
    unpack2(c2[3], o[6], o[7]);
    #pragma unroll
    for (int d = 0; d < 8; d++) o[d] *= inv;

    const int hh = bh & (Hc - 1);
    const int b  = bh >> 4;
    float* op = ctx + ((size_t)(b * Lc + q)) * Dc + hh * DHc;
    *(float4*)op       = make_float4(o[0], o[1], o[2], o[3]);
    *(float4*)(op + 4) = make_float4(o[4], o[5], o[6], o[7]);
}

// ---------------------------------------------------------------------------
// Launch
// ---------------------------------------------------------------------------
extern "C" void kernel_launch(void* const* d_in, const int* in_sizes, int n_in,
                              void* d_out, int out_size)
{
    const float* x         = (const float*)d_in[0];
    const float* conv_w    = (const float*)d_in[1];
    const float* conv_b    = (const float*)d_in[2];
    const float* bn_g      = (const float*)d_in[3];
    const float* bn_b      = (const float*)d_in[4];
    const float* bn_rm     = (const float*)d_in[5];
    const float* bn_rv     = (const float*)d_in[6];
    const float* in_proj_w = (const float*)d_in[7];
    const float* in_proj_b = (const float*)d_in[8];
    const float* out_w     = (const float*)d_in[9];
    const float* out_b     = (const float*)d_in[10];
    const float* ff_w1     = (const float*)d_in[11];
    const float* ff_b1     = (const float*)d_in[12];
    const float* ff_w2     = (const float*)d_in[13];
    const float* ff_b2     = (const float*)d_in[14];
    const float* fc_w      = (const float*)d_in[15];
    const float* fc_b      = (const float*)d_in[16];
    float* out = (float*)d_out;

    float *h, *q, *kb, *vb, *ctx, *ao, *f, *g2, *pe;
    cudaGetSymbolAddress((void**)&h,   g_h);
    cudaGetSymbolAddress((void**)&q,   g_q);
    cudaGetSymbolAddress((void**)&kb,  g_kb);
    cudaGetSymbolAddress((void**)&vb,  g_vb);
    cudaGetSymbolAddress((void**)&ctx, g_ctx);
    cudaGetSymbolAddress((void**)&ao,  g_ao);
    cudaGetSymbolAddress((void**)&f,   g_f);
    cudaGetSymbolAddress((void**)&g2,  g_g2);
    cudaGetSymbolAddress((void**)&pe,  g_pe);

    // 0) positional encoding
    pe_kernel<<<Lc, Dc>>>(pe);

    // 1) conv(k=1)+relu+BN+pe : grid (1,128), single wave
    gemm_k<2><<<dim3(1, Mrows / 64), 256>>>(x, conv_w, conv_b, h,
        Mrows, Dc, DINc, bn_g, bn_b, bn_rm, bn_rv, pe, nullptr, nullptr);

    // 2) qkv projection, scatter to [B,H,L,8] : grid (3,128)
    gemm_k<3><<<dim3(3, Mrows / 64), 256>>>(h, in_proj_w, in_proj_b, q,
        Mrows, 3 * Dc, Dc, nullptr, nullptr, nullptr, nullptr, nullptr, kb, vb);

    // 3) local-window attention -> ctx [B,L,128] : grid (16,64)
    attn_kernel<<<dim3(Lc / AQ, Bc * Hc), AQ>>>(q, kb, vb, ctx);

    // 4) out projection
    gemm_k<0><<<dim3(1, Mrows / 64), 256>>>(ctx, out_w, out_b, ao,
        Mrows, Dc, Dc, nullptr, nullptr, nullptr, nullptr, nullptr, nullptr, nullptr);

    // 5) ffn layer 1 (relu)
    gemm_k<1><<<dim3(1, Mrows / 64), 256>>>(ao, ff_w1, ff_b1, f,
        Mrows, DFFc, Dc, nullptr, nullptr, nullptr, nullptr, nullptr, nullptr, nullptr);

    // 6) ffn layer 2
    gemm_k<0><<<dim3(1, Mrows / 64), 256>>>(f, ff_w2, ff_b2, g2,
        Mrows, Dc, DFFc, nullptr, nullptr, nullptr, nullptr, nullptr, nullptr, nullptr);

    // 7) final head -> [8192,80]
    gemm_k<0><<<dim3(1, Mrows / 64), 256>>>(g2, fc_w, fc_b, out,
        Mrows, DINc, Dc, nullptr, nullptr, nullptr, nullptr, nullptr, nullptr, nullptr);
}